// round 2
// baseline (speedup 1.0000x reference)
#include <cuda_runtime.h>
#include <cstdint>

// ---------------------------------------------------------------------------
// ChebGcnDecoder: FC(128->512 relu) -> FC(512->110592) -> reshape (B,864,128)
//  -> 4x [ChebConv(K=3) + lrelu + repeat2]  -> ChebConv -> perm -> slice 6890
// Feature layout everywhere: (node, batch, channel) row-major, so every GEMM
// is (n*B x ci) @ (ci x co) row-major and propagation moves contiguous rows.
// ---------------------------------------------------------------------------

#define LRELU_S 0.2f

// Scratch (static __device__ arrays; no allocation allowed)
__device__ float g_T[84934656];     // [T0 | T1 | T2], each up to 28,311,552 floats
__device__ float g_out[14155776];   // per-layer GEMM output (max B*n*co = 14.2M)
__device__ float g_h1[65536];       // FC1 output 128x512
__device__ int   g_cnt[6912];
__device__ float g_dinv[6912];
__device__ int   g_off[6913];
__device__ int   g_cur[6912];
__device__ int   g_csrc[41472];
__device__ float g_cw[41472];
__device__ int   g_is64;

// ---------------------------------------------------------------------------
__device__ __forceinline__ int read_idx(const void* p, int i) {
    if (g_is64) return (int)((const long long*)p)[i];
    return ((const int*)p)[i];
}

// Detect int64 vs int32 edge buffers: for little-endian int64 values in
// [0, 6912), every odd 32-bit word is 0. For genuine int32 data the odd words
// are random node ids — all-zero has probability ~0.
__global__ void detect_kernel(const int* w, int nwords) {
    __shared__ int any;
    if (threadIdx.x == 0) any = 0;
    __syncthreads();
    int a = 0;
    for (int i = 1 + 2 * (int)threadIdx.x; i < nwords; i += 2 * blockDim.x) a |= w[i];
    if (a) atomicOr(&any, 1);
    __syncthreads();
    if (threadIdx.x == 0) g_is64 = any ? 0 : 1;
}

__global__ void zero_cnt_kernel(int n) {
    int i = blockIdx.x * blockDim.x + threadIdx.x;
    if (i < n) g_cnt[i] = 0;
}

__global__ void count_kernel(const void* edges, int e) {
    int i = blockIdx.x * blockDim.x + threadIdx.x;
    if (i < e) atomicAdd(&g_cnt[read_idx(edges, e + i)], 1);
}

__global__ void dinv_kernel(int n) {
    int i = blockIdx.x * blockDim.x + threadIdx.x;
    if (i < n) g_dinv[i] = (g_cnt[i] > 0) ? rsqrtf((float)g_cnt[i]) : 0.0f;
}

// One-block exclusive scan over up to 6912 counts -> g_off (n+1), g_cur copy.
__global__ void scan_kernel(int n) {
    __shared__ int partial[1024];
    int tid = threadIdx.x;
    int C = (n + 1023) / 1024;   // <= 7
    int start = tid * C;
    int local[8];
    int s = 0;
    for (int i = 0; i < C; i++) {
        int idx = start + i;
        int v = (idx < n) ? g_cnt[idx] : 0;
        local[i] = s;
        s += v;
    }
    partial[tid] = s;
    __syncthreads();
    for (int d = 1; d < 1024; d <<= 1) {
        int t = (tid >= d) ? partial[tid - d] : 0;
        __syncthreads();
        if (tid >= d) partial[tid] += t;
        __syncthreads();
    }
    int base = (tid > 0) ? partial[tid - 1] : 0;
    for (int i = 0; i < C; i++) {
        int idx = start + i;
        if (idx < n) {
            int o = base + local[i];
            g_off[idx] = o;
            g_cur[idx] = o;
        }
    }
    if (tid == 1023) g_off[n] = partial[1023];
}

__global__ void fill_kernel(const void* edges, int e) {
    int i = blockIdx.x * blockDim.x + threadIdx.x;
    if (i < e) {
        int s = read_idx(edges, i);
        int d = read_idx(edges, e + i);
        int p = atomicAdd(&g_cur[d], 1);
        g_csrc[p] = s;
        g_cw[p] = -g_dinv[s] * g_dinv[d];
    }
}

// out[v][j] = scale * sum_{in-edges of v} w * in[src][j]  - (sub ? sub[v][j] : 0)
// R = B*ci (row length, multiple of 256). grid = (R/256, n).
__global__ void prop_kernel(float* __restrict__ out, const float* __restrict__ in,
                            const float* __restrict__ sub, float scale, int R) {
    int v = blockIdx.y;
    int j = blockIdx.x * blockDim.x + threadIdx.x;
    float acc = 0.0f;
    int s = g_off[v], t = g_off[v + 1];
    for (int q = s; q < t; q++)
        acc += g_cw[q] * in[(size_t)g_csrc[q] * R + j];
    float r = scale * acc;
    if (sub) r -= sub[(size_t)v * R + j];
    out[(size_t)v * R + j] = r;
}

// ---------------------------------------------------------------------------
// Generic 3-block SGEMM: C(MxN) = [A_0|A_1|..|A_{nblk-1}] (M x nblk*ci) @ W + bias
// A_p[m][k] lives at A[p*S + m*ci + k].  W is row-major (nblk*ci x N).
// mode: 0 = bias, 1 = bias+relu, 2 = bias+lrelu,
//       3 = bias + FC2-transpose write into (v,b,c) layout (B=128, C=128).
// Requires M % 128 == 0 and K % 16 == 0 (holds for every call here).
// ---------------------------------------------------------------------------
#define BM 128
#define BN 64
#define BK 16

__global__ __launch_bounds__(256)
void gemm3_kernel(const float* __restrict__ A, int S, int ci, int nblk,
                  const float* __restrict__ W, const float* __restrict__ bias,
                  float* __restrict__ out, int M, int N, int mode) {
    __shared__ float As[BK][BM + 4];
    __shared__ float Ws[BK][BN];
    int tid = threadIdx.x;
    int tx = tid & 15, ty = tid >> 4;
    int m0 = blockIdx.y * BM, n0 = blockIdx.x * BN;
    int K = nblk * ci;

    float acc[8][4];
#pragma unroll
    for (int i = 0; i < 8; i++)
#pragma unroll
        for (int j = 0; j < 4; j++) acc[i][j] = 0.0f;

    for (int k0 = 0; k0 < K; k0 += BK) {
#pragma unroll
        for (int r = 0; r < 8; r++) {
            int idx = tid + r * 256;        // 0..2047
            int m = idx >> 4;
            int k = idx & 15;
            int kg = k0 + k;
            int p = kg / ci;
            int off = kg - p * ci;
            As[k][m] = A[(size_t)p * S + (size_t)(m0 + m) * ci + off];
        }
#pragma unroll
        for (int r = 0; r < 4; r++) {
            int idx = tid + r * 256;        // 0..1023
            int k = idx >> 6;
            int n = idx & 63;
            float v = 0.0f;
            if (n0 + n < N) v = W[(size_t)(k0 + k) * N + (n0 + n)];
            Ws[k][n] = v;
        }
        __syncthreads();
#pragma unroll
        for (int k = 0; k < BK; k++) {
            float a[8], w[4];
#pragma unroll
            for (int i = 0; i < 8; i++) a[i] = As[k][ty * 8 + i];
#pragma unroll
            for (int j = 0; j < 4; j++) w[j] = Ws[k][tx * 4 + j];
#pragma unroll
            for (int i = 0; i < 8; i++)
#pragma unroll
                for (int j = 0; j < 4; j++) acc[i][j] += a[i] * w[j];
        }
        __syncthreads();
    }

#pragma unroll
    for (int i = 0; i < 8; i++) {
        int m = m0 + ty * 8 + i;
#pragma unroll
        for (int j = 0; j < 4; j++) {
            int n = n0 + tx * 4 + j;
            if (n < N) {
                float v = acc[i][j] + bias[n];
                if (mode == 1) v = v > 0.0f ? v : 0.0f;
                else if (mode == 2) v = v >= 0.0f ? v : LRELU_S * v;
                if (mode == 3) {
                    // n = vnode*128 + c ; m = b  -> T0[(vnode*128 + b)*128 + c]
                    out[(size_t)((n >> 7) * 128 + m) * 128 + (n & 127)] = v;
                } else {
                    out[(size_t)m * N + n] = v;
                }
            }
        }
    }
}

// Row-duplicating copy: dst row i <- src row (i >> shift). row = B*co.
__global__ void expand_kernel(float* __restrict__ dst, const float* __restrict__ src,
                              int row, int total, int shift) {
    int i = blockIdx.x * blockDim.x + threadIdx.x;
    if (i < total) {
        int v = i / row;
        int r = i - v * row;
        dst[i] = src[(size_t)(v >> shift) * row + r];
    }
}

// out[b][u][k] = h[(perm[u]*128 + b)*3 + k], u < 6890
__global__ void final_kernel(float* __restrict__ out, const float* __restrict__ h,
                             const void* __restrict__ perm) {
    int i = blockIdx.x * blockDim.x + threadIdx.x;
    const int TOT = 128 * 6890 * 3;
    if (i < TOT) {
        int b = i / (6890 * 3);
        int r = i - b * (6890 * 3);
        int u = r / 3;
        int k = r - u * 3;
        int v = read_idx(perm, u);
        out[i] = h[(size_t)(v * 128 + b) * 3 + k];
    }
}

// ---------------------------------------------------------------------------
extern "C" void kernel_launch(void* const* d_in, const int* in_sizes, int n_in,
                              void* d_out, int out_size) {
    const float* x   = (const float*)d_in[0];
    const float* fw1 = (const float*)d_in[1];
    const float* fb1 = (const float*)d_in[2];
    const float* fw2 = (const float*)d_in[3];
    const float* fb2 = (const float*)d_in[4];
    const float* W[5];
    const float* bb[5];
    for (int i = 0; i < 5; i++) {
        W[i]  = (const float*)d_in[5 + 2 * i];
        bb[i] = (const float*)d_in[6 + 2 * i];
    }
    const void* edges[4];
    for (int i = 0; i < 4; i++) edges[i] = d_in[15 + i];
    const void* perm = d_in[19];
    float* out = (float*)d_out;

    float *T, *Ob, *H1;
    cudaGetSymbolAddress((void**)&T,  g_T);
    cudaGetSymbolAddress((void**)&Ob, g_out);
    cudaGetSymbolAddress((void**)&H1, g_h1);

    // dtype sniff for index arrays (edge0 has 5184 edges -> 5184 words safe either way)
    detect_kernel<<<1, 256>>>((const int*)edges[0], 5184);

    // FC1: (128x128)@(128x512)+b, relu
    gemm3_kernel<<<dim3(512 / BN, 1), 256>>>(x, 0, 128, 1, fw1, fb1, H1, 128, 512, 1);
    // FC2: (128x512)@(512x110592)+b, written transposed into T0 as (v,b,c)
    gemm3_kernel<<<dim3(110592 / BN, 1), 256>>>(H1, 0, 512, 1, fw2, fb2, T, 128, 110592, 3);

    const int ns[5]   = {864, 1728, 3456, 6912, 6912};
    const int cis[5]  = {128, 128, 64, 32, 16};
    const int cos_[5] = {128, 64, 32, 16, 3};
    const int eidx[5] = {0, 1, 2, 3, 3};
    const int egn[4]  = {864, 1728, 3456, 6912};

    for (int l = 0; l < 5; l++) {
        int n  = ns[l];
        int ci = cis[l];
        int co = cos_[l];
        const void* eg = edges[eidx[l]];
        int e = 6 * egn[eidx[l]];
        int R = 128 * ci;                 // row length, multiple of 256
        size_t Ssz = (size_t)n * R;       // block stride within g_T
        int M = n * 128;

        // Build CSR-by-dst + normalization
        zero_cnt_kernel<<<(n + 255) / 256, 256>>>(n);
        count_kernel<<<(e + 255) / 256, 256>>>(eg, e);
        dinv_kernel<<<(n + 255) / 256, 256>>>(n);
        scan_kernel<<<1, 1024>>>(n);
        fill_kernel<<<(e + 255) / 256, 256>>>(eg, e);

        // Tx1 = prop(Tx0); Tx2 = 2*prop(Tx1) - Tx0
        prop_kernel<<<dim3(R / 256, n), 256>>>(T + Ssz, T, nullptr, 1.0f, R);
        prop_kernel<<<dim3(R / 256, n), 256>>>(T + 2 * Ssz, T + Ssz, T, 2.0f, R);

        // out = [Tx0|Tx1|Tx2] @ stacked W (3ci x co) + b, (l)relu
        int mode = (l < 4) ? 2 : 0;
        gemm3_kernel<<<dim3((co + BN - 1) / BN, M / BM), 256>>>(
            T, (int)Ssz, ci, 3, W[l], bb[l], Ob, M, co, mode);

        if (l < 3) {
            int row = 128 * co;
            int total = 2 * n * row;      // repeat(2, axis=1)
            expand_kernel<<<(total + 255) / 256, 256>>>(T, Ob, row, total, 1);
        } else if (l == 3) {
            int row = 128 * co;
            int total = n * row;          // plain copy into next T0
            expand_kernel<<<(total + 255) / 256, 256>>>(T, Ob, row, total, 0);
        } else {
            int total = 128 * 6890 * 3;
            final_kernel<<<(total + 255) / 256, 256>>>(out, Ob, perm);
        }
    }
}